// round 7
// baseline (speedup 1.0000x reference)
#include <cuda_runtime.h>
#include <math.h>

#define NB 8
#define C 96
#define G 4
#define CG 24
#define HH 56
#define HW 3136
#define P 25088            // NB*HW
#define HD 384
#define NCHW (NB*C*HW)     // 2408448
#define EPSF 1e-12f

typedef unsigned long long ull;

__device__ __forceinline__ ull fma2(ull a, ull b, ull c){
    ull d; asm("fma.rn.f32x2 %0, %1, %2, %3;" : "=l"(d) : "l"(a), "l"(b), "l"(c));
    return d;
}
__device__ __forceinline__ ull dup2(float v){
    ull d; asm("mov.b64 %0, {%1, %1};" : "=l"(d) : "f"(v));
    return d;
}
__device__ __forceinline__ void unpack2(ull a, float& lo, float& hi){
    asm("mov.b64 {%0, %1}, %2;" : "=f"(lo), "=f"(hi) : "l"(a));
}

// ---------------- device scratch ----------------
__device__ float g_xnn[NCHW];     // relu(LN1(x)) channel-normalized
__device__ float g_h[NCHW];       // NNMF h (unnormalized; normalized on read)
__device__ float g_t[NCHW];       // ratio buffer, later x2 = x + attn
__device__ float g_lncf[NCHW];    // LN2 output, [c][p] channels-first
__device__ float g_hid[P*HD];     // MLP hidden
__device__ float g_wf2[8*2592];   // fwd weights  [g*2+hf][(ci*9+t)*12 + k]
__device__ float g_wb2[8*2592];   // bwd weights  [g*2+hf][(o*9+(8-t))*12 + k]
__device__ float g_sum8[8*P];     // per-(g,half) per-pixel partial sums of h

__device__ __forceinline__ float gelu_exact(float v){
    return 0.5f * v * (1.0f + erff(v * 0.70710678118654752f));
}

// ---------------- weight prep: |w| L1-normalized per out-channel ----------
__global__ void prep_w_kernel(const float* __restrict__ wn){
    int o = blockIdx.x;          // 0..95 global out channel
    int lane = threadIdx.x;      // 0..31
    float s = 0.f;
    for (int i = lane; i < 216; i += 32) s += fabsf(wn[o*216 + i]);
    #pragma unroll
    for (int off = 16; off; off >>= 1) s += __shfl_xor_sync(0xffffffffu, s, off);
    float inv = 1.0f / (s + EPSF);
    int g = o / 24, oo = o % 24;
    for (int i = lane; i < 216; i += 32){
        int ci = i / 9, t = i % 9;
        float v = fabsf(wn[o*216 + i]) * inv;
        g_wf2[(g*2 + oo/12)*2592 + (ci*9 + t)*12 + (oo%12)] = v;
        g_wb2[(g*2 + ci/12)*2592 + (oo*9 + (8 - t))*12 + (ci%12)] = v;
    }
}

// ---- LN1 (channels-first) + relu + channel-normalize; init h, sums ------
__global__ void ln1_kernel(const float* __restrict__ x,
                           const float* __restrict__ lw,
                           const float* __restrict__ lb){
    int p = blockIdx.x*256 + threadIdx.x;
    if (p >= P) return;
    int n = p / HW, hw = p % HW;
    const float* xb = x + n*C*HW + hw;
    float s1 = 0.f, s2 = 0.f;
    for (int c = 0; c < C; c++){ float v = xb[c*HW]; s1 += v; s2 += v*v; }
    float u = s1 * (1.0f/96.0f);
    float var = s2 * (1.0f/96.0f) - u*u;
    float rs = rsqrtf(var + 1e-6f);
    float sr = 0.f;
    for (int c = 0; c < C; c++){
        float v = (xb[c*HW] - u) * rs * lw[c] + lb[c];
        sr += fmaxf(v, 0.f);
    }
    float inv = 1.0f / (sr + EPSF);
    float* ob = g_xnn + n*C*HW + hw;
    float* hb = g_h   + n*C*HW + hw;
    for (int c = 0; c < C; c++){
        float v = (xb[c*HW] - u) * rs * lw[c] + lb[c];
        ob[c*HW] = fmaxf(v, 0.f) * inv;
        hb[c*HW] = 1.0f / 96.0f;
    }
    #pragma unroll
    for (int j = 0; j < 8; j++) g_sum8[j*P + p] = 0.125f;  // total = 1
}

// ---- grouped 3x3 conv: tile 8 rows x 56 cols, 2 ADJACENT px/thread ------
// ci processed in 2 stages of 12 (smem diet -> 4 CTAs/SM, 448 blocks resident)
// grid (7 row-tiles, 8 (g,half), 8 n), block 224 = 8 rows x 28 col-pairs.
// MODE 0: transpose-conv of normalized h; epilogue ratio -> g_t (12 co)
// MODE 1: forward conv of ratio; epilogue h *= acc, partial sums -> g_sum8
#define SIN_F   (12*580)            // 6960
#define SW_OFF  SIN_F
#define SINV_OFF (SIN_F + 2592)     // 9552
#define SM_TOT  (SINV_OFF + 580)    // 10132 floats = 40528 B

template<int MODE>
__global__ __launch_bounds__(224, 4) void conv_kernel(){
    extern __shared__ float sm[];
    float* s_in  = sm;
    float* s_w   = sm + SW_OFF;
    float* s_inv = sm + SINV_OFF;
    const int tid = threadIdx.x;
    const int r0 = blockIdx.x * 8;
    const int gh = blockIdx.y;        // g*2 + half
    const int n  = blockIdx.z;
    const int g  = gh >> 1;
    const float* __restrict__ w  = ((MODE == 0) ? g_wb2 : g_wf2) + gh*2592;
    const float* __restrict__ in = (MODE == 0) ? g_h  : g_t;

    for (int i = tid; i < 2592; i += 224) s_w[i] = w[i];

    const int cin_base  = n*96 + g*24;
    const int cout_base = n*96 + g*24 + (gh & 1)*12;
    const int pbase = n*HW;

    if (MODE == 0){
        // per-halo-pixel inverse channel-sum (interior cols; edges unused)
        for (int i = tid; i < 580; i += 224){
            int r   = i / 58;
            int col = i - r*58 - 1;
            int grow = r0 - 1 + r;
            float iv = 0.f;
            if ((unsigned)grow < 56u && (unsigned)col < 56u){
                int q = pbase + grow*56 + col;
                float s = 0.f;
                #pragma unroll
                for (int j = 0; j < 8; j++) s += g_sum8[j*P + q];
                iv = 1.0f / (s + EPSF);
            }
            s_inv[i] = iv;
        }
    }

    // per-thread loader coords (guard hoisted; no divides in hot path)
    const int c4  = tid % 14;          // float4 slot within row
    const int rsl = tid / 14;          // smem row slot 0..15 (active <10)
    const int grow = r0 - 1 + rsl;
    const bool rok = (rsl < 10) && ((unsigned)grow < 56u);
    float iv0=0,iv1=0,iv2=0,iv3=0;

    const int cx = tid % 28;          // col-pair index: pixels 2cx, 2cx+1
    const int ty = tid / 28;          // 0..7
    const float* sbase = s_in + ty*58 + 2*cx;
    ull acc[12];                      // [0..5] px0 co-pairs, [6..11] px1
    #pragma unroll
    for (int i = 0; i < 12; i++) acc[i] = 0ULL;

    #pragma unroll
    for (int st = 0; st < 2; st++){
        // sync: stage0 covers s_inv; stage1 guards buffer overwrite
        __syncthreads();

        // edge halo columns are outside the image: always zero
        for (int i = tid; i < 240; i += 224){
            int ci = i / 20, rem = i - ci*20;
            int row = rem >> 1, ecol = (rem & 1) * 57;
            s_in[ci*580 + row*58 + ecol] = 0.f;
        }
        // interior: vectorized LDG.128 of 12 channels
        if (rsl < 10){
            if (MODE == 0 && rok && st == 0){
                const float* sv = s_inv + rsl*58 + 1 + c4*4;
                iv0 = sv[0]; iv1 = sv[1]; iv2 = sv[2]; iv3 = sv[3];
            }
            const float* gb = in + (size_t)(cin_base + st*12)*HW + grow*56 + c4*4;
            float* sb = s_in + rsl*58 + 1 + c4*4;
            #pragma unroll 4
            for (int ci = 0; ci < 12; ci++){
                float4 v = make_float4(0.f,0.f,0.f,0.f);
                if (rok) v = *(const float4*)(gb + ci*HW);
                if (MODE == 0){ v.x*=iv0; v.y*=iv1; v.z*=iv2; v.w*=iv3; }
                float* s = sb + ci*580;
                s[0]=v.x; s[1]=v.y; s[2]=v.z; s[3]=v.w;
            }
        }
        __syncthreads();

        const float* swst = s_w + st*12*108;   // (st*12+ci)*9*12
        for (int ci = 0; ci < 12; ci++){
            const float* si = sbase + ci*580;
            float v[3][4];
            #pragma unroll
            for (int dr = 0; dr < 3; dr++){
                float2 a = *(const float2*)(si + dr*58);
                float2 b = *(const float2*)(si + dr*58 + 2);
                v[dr][0]=a.x; v[dr][1]=a.y; v[dr][2]=b.x; v[dr][3]=b.y;
            }
            #pragma unroll
            for (int t = 0; t < 9; t++){
                const int dr = t/3, dc = t%3;
                ull d0 = dup2(v[dr][dc]);
                ull d1 = dup2(v[dr][dc+1]);
                const ulonglong2* wp = (const ulonglong2*)(swst + (ci*9 + t)*12);
                ulonglong2 wa = wp[0];
                ulonglong2 wb = wp[1];
                ulonglong2 wc = wp[2];
                acc[0]  = fma2(d0, wa.x, acc[0]);
                acc[1]  = fma2(d0, wa.y, acc[1]);
                acc[2]  = fma2(d0, wb.x, acc[2]);
                acc[3]  = fma2(d0, wb.y, acc[3]);
                acc[4]  = fma2(d0, wc.x, acc[4]);
                acc[5]  = fma2(d0, wc.y, acc[5]);
                acc[6]  = fma2(d1, wa.x, acc[6]);
                acc[7]  = fma2(d1, wa.y, acc[7]);
                acc[8]  = fma2(d1, wb.x, acc[8]);
                acc[9]  = fma2(d1, wb.y, acc[9]);
                acc[10] = fma2(d1, wc.x, acc[10]);
                acc[11] = fma2(d1, wc.y, acc[11]);
            }
        }
    }

    float af0[12], af1[12];
    #pragma unroll
    for (int i = 0; i < 6; i++){
        unpack2(acc[i],   af0[2*i], af0[2*i+1]);
        unpack2(acc[6+i], af1[2*i], af1[2*i+1]);
    }

    const int pix0 = (r0 + ty)*56 + 2*cx;     // even -> float2-aligned
    if (MODE == 0){
        #pragma unroll
        for (int k = 0; k < 12; k++){
            int idx = (cout_base + k)*HW + pix0;
            float2 xn = *(const float2*)(g_xnn + idx);
            float2 o;
            o.x = xn.x / (af0[k] + EPSF);
            o.y = xn.y / (af1[k] + EPSF);
            *(float2*)(g_t + idx) = o;
        }
    } else {
        float s0 = 0.f, s1 = 0.f;
        #pragma unroll
        for (int k = 0; k < 12; k++){
            int idx = (cout_base + k)*HW + pix0;
            float2 hv = *(const float2*)(g_h + idx);
            hv.x *= af0[k];
            hv.y *= af1[k];
            *(float2*)(g_h + idx) = hv;
            s0 += hv.x; s1 += hv.y;
        }
        float2 sv; sv.x = s0; sv.y = s1;
        *(float2*)(g_sum8 + gh*P + pbase + pix0) = sv;
    }
}

// ------- fused: x2 = x + h_norm  ->  LN2 over channels -> g_lncf [c][p] ---
__global__ void resid_ln2_kernel(const float* __restrict__ x,
                                 const float* __restrict__ lw,
                                 const float* __restrict__ lb){
    int p = blockIdx.x*256 + threadIdx.x;
    if (p >= P) return;
    int n = p / HW, hw = p % HW;
    float s = 0.f;
    #pragma unroll
    for (int j = 0; j < 8; j++) s += g_sum8[j*P + p];
    float inv = 1.0f / (s + EPSF);
    const float* xb = x   + n*C*HW + hw;
    const float* hb = g_h + n*C*HW + hw;
    float* tb = g_t + n*C*HW + hw;
    float s1 = 0.f, s2 = 0.f;
    for (int c = 0; c < C; c++){
        float v = xb[c*HW] + hb[c*HW]*inv;
        tb[c*HW] = v;
        s1 += v; s2 += v*v;
    }
    float u = s1 * (1.0f/96.0f);
    float var = s2 * (1.0f/96.0f) - u*u;
    float rs = rsqrtf(var + 1e-5f);
    for (int c = 0; c < C; c++)
        g_lncf[c*P + p] = (tb[c*HW] - u) * rs * lw[c] + lb[c];
}

// ---------------- GEMM1: [P,96] x [96,384] -> gelu -> g_hid --------------
__global__ __launch_bounds__(256) void gemm1_kernel(const float* __restrict__ w1,
                                                    const float* __restrict__ b1){
    __shared__ float As[96*68];
    __shared__ float Bs[96*32];
    const int tid = threadIdx.x;
    const int p0 = blockIdx.x * 64;
    const int n0 = blockIdx.y * 32;
    for (int i = tid; i < 6144; i += 256){
        int c = i >> 6, m = i & 63;
        As[c*68 + m] = g_lncf[c*P + p0 + m];
    }
    for (int i = tid; i < 3072; i += 256){
        int c = i >> 5, j = i & 31;
        Bs[c*32 + j] = w1[c*384 + n0 + j];
    }
    __syncthreads();
    const int tm = tid >> 4, tn = tid & 15;
    ull acc[4];
    #pragma unroll
    for (int i = 0; i < 4; i++) acc[i] = 0ULL;
    #pragma unroll 4
    for (int k = 0; k < 96; k++){
        float4 a = *(const float4*)(As + k*68 + tm*4);
        ull b = *(const ull*)(Bs + k*32 + tn*2);
        acc[0] = fma2(dup2(a.x), b, acc[0]);
        acc[1] = fma2(dup2(a.y), b, acc[1]);
        acc[2] = fma2(dup2(a.z), b, acc[2]);
        acc[3] = fma2(dup2(a.w), b, acc[3]);
    }
    int m = p0 + tm*4;
    int j = n0 + tn*2;
    float bj0 = b1[j], bj1 = b1[j+1];
    #pragma unroll
    for (int ii = 0; ii < 4; ii++){
        float a0, a1; unpack2(acc[ii], a0, a1);
        g_hid[(m+ii)*384 + j]     = gelu_exact(a0 + bj0);
        g_hid[(m+ii)*384 + j + 1] = gelu_exact(a1 + bj1);
    }
}

// ---- GEMM2: [P,384] x [384,96] + b2 + residual -> out (NCHW) -----------
__global__ __launch_bounds__(256) void gemm2_kernel(const float* __restrict__ w2,
                                                    const float* __restrict__ b2,
                                                    float* __restrict__ out){
    __shared__ float As[32*68];
    __shared__ float Bs[32*96];
    const int tid = threadIdx.x;
    const int p0 = blockIdx.x * 64;
    const int nimg = p0 / HW;
    const int hw0  = p0 % HW;
    const int tm = tid >> 4, tn = tid & 15;
    ull acc[4][3];
    #pragma unroll
    for (int ii = 0; ii < 4; ii++)
        #pragma unroll
        for (int jp = 0; jp < 3; jp++) acc[ii][jp] = 0ULL;
    for (int kb = 0; kb < 12; kb++){
        for (int i = tid; i < 2048; i += 256){
            int m = i >> 5, k = i & 31;
            As[k*68 + m] = g_hid[(p0 + m)*384 + kb*32 + k];
        }
        for (int i = tid; i < 3072; i += 256){
            int k = i / 96, c = i - k*96;
            Bs[k*96 + c] = w2[(kb*32 + k)*96 + c];
        }
        __syncthreads();
        #pragma unroll 4
        for (int k = 0; k < 32; k++){
            float4 a = *(const float4*)(As + k*68 + tm*4);
            const float* bp = Bs + k*96 + tn*6;
            ull b0 = *(const ull*)(bp);
            ull b1v = *(const ull*)(bp + 2);
            ull b2v = *(const ull*)(bp + 4);
            ull a0 = dup2(a.x), a1 = dup2(a.y), a2 = dup2(a.z), a3 = dup2(a.w);
            acc[0][0] = fma2(a0, b0, acc[0][0]);
            acc[0][1] = fma2(a0, b1v, acc[0][1]);
            acc[0][2] = fma2(a0, b2v, acc[0][2]);
            acc[1][0] = fma2(a1, b0, acc[1][0]);
            acc[1][1] = fma2(a1, b1v, acc[1][1]);
            acc[1][2] = fma2(a1, b2v, acc[1][2]);
            acc[2][0] = fma2(a2, b0, acc[2][0]);
            acc[2][1] = fma2(a2, b1v, acc[2][1]);
            acc[2][2] = fma2(a2, b2v, acc[2][2]);
            acc[3][0] = fma2(a3, b0, acc[3][0]);
            acc[3][1] = fma2(a3, b1v, acc[3][1]);
            acc[3][2] = fma2(a3, b2v, acc[3][2]);
        }
        __syncthreads();
    }
    const int cbase = tn*6;
    #pragma unroll
    for (int jp = 0; jp < 3; jp++){
        int c0 = cbase + 2*jp;
        float bc0 = b2[c0], bc1 = b2[c0+1];
        #pragma unroll
        for (int ii = 0; ii < 4; ii++){
            float v0, v1; unpack2(acc[ii][jp], v0, v1);
            int hw = hw0 + tm*4 + ii;
            int gi0 = (nimg*96 + c0)*HW + hw;
            int gi1 = (nimg*96 + c0 + 1)*HW + hw;
            out[gi0] = v0 + bc0 + g_t[gi0];
            out[gi1] = v1 + bc1 + g_t[gi1];
        }
    }
}

// ---------------- launch ----------------
extern "C" void kernel_launch(void* const* d_in, const int* in_sizes, int n_in,
                              void* d_out, int out_size){
    const float* x    = (const float*)d_in[0];
    const float* ln1w = (const float*)d_in[1];
    const float* ln1b = (const float*)d_in[2];
    const float* wn   = (const float*)d_in[3];
    const float* ln2w = (const float*)d_in[4];
    const float* ln2b = (const float*)d_in[5];
    const float* w1   = (const float*)d_in[6];
    const float* b1   = (const float*)d_in[7];
    const float* w2   = (const float*)d_in[8];
    const float* b2   = (const float*)d_in[9];
    float* out = (float*)d_out;

    const int CONV_SMEM = SM_TOT * 4;   // 40528 B
    cudaFuncSetAttribute(conv_kernel<0>, cudaFuncAttributeMaxDynamicSharedMemorySize, CONV_SMEM);
    cudaFuncSetAttribute(conv_kernel<1>, cudaFuncAttributeMaxDynamicSharedMemorySize, CONV_SMEM);

    prep_w_kernel<<<96, 32>>>(wn);
    ln1_kernel<<<98, 256>>>(x, ln1w, ln1b);

    dim3 cgrid(7, 8, 8);   // 448 blocks, all resident at 4 CTAs/SM
    for (int it = 0; it < 25; ++it){
        conv_kernel<0><<<cgrid, 224, CONV_SMEM>>>();   // recon -> ratio
        conv_kernel<1><<<cgrid, 224, CONV_SMEM>>>();   // h update + partial sums
    }

    resid_ln2_kernel<<<98, 256>>>(x, ln2w, ln2b);
    gemm1_kernel<<<dim3(392, 12), 256>>>(w1, b1);
    gemm2_kernel<<<392, 256>>>(w2, b2, out);
}

// round 8
// speedup vs baseline: 1.1767x; 1.1767x over previous
#include <cuda_runtime.h>
#include <math.h>

#define NB 8
#define C 96
#define G 4
#define CG 24
#define HH 56
#define HW 3136
#define P 25088            // NB*HW
#define HD 384
#define NCHW (NB*C*HW)     // 2408448
#define EPSF 1e-12f

typedef unsigned long long ull;

__device__ __forceinline__ ull fma2(ull a, ull b, ull c){
    ull d; asm("fma.rn.f32x2 %0, %1, %2, %3;" : "=l"(d) : "l"(a), "l"(b), "l"(c));
    return d;
}
__device__ __forceinline__ ull dup2(float v){
    ull d; asm("mov.b64 %0, {%1, %1};" : "=l"(d) : "f"(v));
    return d;
}
__device__ __forceinline__ void unpack2(ull a, float& lo, float& hi){
    asm("mov.b64 {%0, %1}, %2;" : "=f"(lo), "=f"(hi) : "l"(a));
}
// warp-uniform 16B read-only global load (1 line -> ~1 L1 wavefront)
__device__ __forceinline__ void ldg2(const float* p, ull& a, ull& b){
    asm("ld.global.nc.v2.u64 {%0, %1}, [%2];" : "=l"(a), "=l"(b) : "l"(p));
}

// ---------------- device scratch ----------------
__device__ float g_xnn[NCHW];     // relu(LN1(x)) channel-normalized
__device__ float g_h[NCHW];       // NNMF h (unnormalized; normalized on read)
__device__ float g_t[NCHW];       // ratio buffer, later x2 = x + attn
__device__ float g_lncf[NCHW];    // LN2 output, [c][p] channels-first
__device__ float g_hid[P*HD];     // MLP hidden
__device__ __align__(16) float g_wf2[8*2592];  // fwd  [g*2+hf][(ci*9+t)*12 + k]
__device__ __align__(16) float g_wb2[8*2592];  // bwd  [g*2+hf][(o*9+(8-t))*12 + k]
__device__ float g_sum8[8*P];     // per-(g,half) per-pixel partial sums of h

__device__ __forceinline__ float gelu_exact(float v){
    return 0.5f * v * (1.0f + erff(v * 0.70710678118654752f));
}

// ---------------- weight prep: |w| L1-normalized per out-channel ----------
__global__ void prep_w_kernel(const float* __restrict__ wn){
    int o = blockIdx.x;          // 0..95 global out channel
    int lane = threadIdx.x;      // 0..31
    float s = 0.f;
    for (int i = lane; i < 216; i += 32) s += fabsf(wn[o*216 + i]);
    #pragma unroll
    for (int off = 16; off; off >>= 1) s += __shfl_xor_sync(0xffffffffu, s, off);
    float inv = 1.0f / (s + EPSF);
    int g = o / 24, oo = o % 24;
    for (int i = lane; i < 216; i += 32){
        int ci = i / 9, t = i % 9;
        float v = fabsf(wn[o*216 + i]) * inv;
        g_wf2[(g*2 + oo/12)*2592 + (ci*9 + t)*12 + (oo%12)] = v;
        g_wb2[(g*2 + ci/12)*2592 + (oo*9 + (8 - t))*12 + (ci%12)] = v;
    }
}

// ---- LN1 (channels-first) + relu + channel-normalize; init h, sums ------
__global__ void ln1_kernel(const float* __restrict__ x,
                           const float* __restrict__ lw,
                           const float* __restrict__ lb){
    int p = blockIdx.x*256 + threadIdx.x;
    if (p >= P) return;
    int n = p / HW, hw = p % HW;
    const float* xb = x + n*C*HW + hw;
    float s1 = 0.f, s2 = 0.f;
    for (int c = 0; c < C; c++){ float v = xb[c*HW]; s1 += v; s2 += v*v; }
    float u = s1 * (1.0f/96.0f);
    float var = s2 * (1.0f/96.0f) - u*u;
    float rs = rsqrtf(var + 1e-6f);
    float sr = 0.f;
    for (int c = 0; c < C; c++){
        float v = (xb[c*HW] - u) * rs * lw[c] + lb[c];
        sr += fmaxf(v, 0.f);
    }
    float inv = 1.0f / (sr + EPSF);
    float* ob = g_xnn + n*C*HW + hw;
    float* hb = g_h   + n*C*HW + hw;
    for (int c = 0; c < C; c++){
        float v = (xb[c*HW] - u) * rs * lw[c] + lb[c];
        ob[c*HW] = fmaxf(v, 0.f) * inv;
        hb[c*HW] = 1.0f / 96.0f;
    }
    #pragma unroll
    for (int j = 0; j < 8; j++) g_sum8[j*P + p] = 0.125f;  // total = 1
}

// ---- grouped 3x3 conv: tile 8 rows x 56 cols, 2 ADJACENT px/thread ------
// grid (7 row-tiles, 8 (g,half), 8 n), block 224 = 8 rows x 28 col-pairs.
// Weights read via warp-uniform ld.global.nc (L1-resident, 1 wf/16B) —
// no smem staging for weights.
// MODE 0: transpose-conv of normalized h; epilogue ratio -> g_t (12 co)
// MODE 1: forward conv of ratio; epilogue h *= acc, partial sums -> g_sum8
#define SIN_F   (24*580)            // 13920
#define SINV_OFF SIN_F              // 13920
#define SM_TOT  (SINV_OFF + 580)    // 14500 floats = 58000 B

template<int MODE>
__global__ __launch_bounds__(224, 3) void conv_kernel(){
    extern __shared__ float sm[];
    float* s_in  = sm;
    float* s_inv = sm + SINV_OFF;
    const int tid = threadIdx.x;
    const int r0 = blockIdx.x * 8;
    const int gh = blockIdx.y;        // g*2 + half
    const int n  = blockIdx.z;
    const int g  = gh >> 1;
    const float* __restrict__ wg = ((MODE == 0) ? g_wb2 : g_wf2) + gh*2592;
    const float* __restrict__ in = (MODE == 0) ? g_h  : g_t;

    const int cin_base  = n*96 + g*24;
    const int cout_base = n*96 + g*24 + (gh & 1)*12;
    const int pbase = n*HW;

    if (MODE == 0){
        // per-halo-pixel inverse channel-sum (interior cols only; edges unused->0)
        for (int i = tid; i < 580; i += 224){
            int r   = i / 58;
            int col = i - r*58 - 1;
            int grow = r0 - 1 + r;
            float iv = 0.f;
            if ((unsigned)grow < 56u && (unsigned)col < 56u){
                int q = pbase + grow*56 + col;
                float s = 0.f;
                #pragma unroll
                for (int j = 0; j < 8; j++) s += g_sum8[j*P + q];
                iv = 1.0f / (s + EPSF);
            }
            s_inv[i] = iv;
        }
        __syncthreads();
    }

    // ---- edge halo columns are outside the image: always zero ----
    for (int i = tid; i < 480; i += 224){
        int ci = i / 20, rem = i - ci*20;
        int row = rem >> 1, ecol = (rem & 1) * 57;
        s_in[ci*580 + row*58 + ecol] = 0.f;
    }

    // ---- interior: vectorized LDG.128, guard hoisted out of ci loop ----
    {
        const int c4  = tid % 14;          // float4 slot within row
        const int rsl = tid / 14;          // smem row slot 0..15 (active <10)
        if (rsl < 10){
            const int grow = r0 - 1 + rsl;
            const bool rok = ((unsigned)grow < 56u);
            float iv0=0,iv1=0,iv2=0,iv3=0;
            if (MODE == 0 && rok){
                const float* sv = s_inv + rsl*58 + 1 + c4*4;
                iv0 = sv[0]; iv1 = sv[1]; iv2 = sv[2]; iv3 = sv[3];
            }
            const float* gb = in + (size_t)cin_base*HW + grow*56 + c4*4;
            float* sb = s_in + rsl*58 + 1 + c4*4;
            #pragma unroll 4
            for (int ci = 0; ci < 24; ci++){
                float4 v = make_float4(0.f,0.f,0.f,0.f);
                if (rok) v = *(const float4*)(gb + ci*HW);
                if (MODE == 0){ v.x*=iv0; v.y*=iv1; v.z*=iv2; v.w*=iv3; }
                float* s = sb + ci*580;
                s[0]=v.x; s[1]=v.y; s[2]=v.z; s[3]=v.w;
            }
        }
    }
    __syncthreads();

    const int cx = tid % 28;          // col-pair index: pixels 2cx, 2cx+1
    const int ty = tid / 28;          // 0..7
    const float* sbase = s_in + ty*58 + 2*cx;
    ull acc[12];                      // [0..5] px0 co-pairs, [6..11] px1
    #pragma unroll
    for (int i = 0; i < 12; i++) acc[i] = 0ULL;

    for (int ci = 0; ci < 24; ci++){
        const float* si = sbase + ci*580;
        float v[3][4];
        #pragma unroll
        for (int dr = 0; dr < 3; dr++){
            float2 a = *(const float2*)(si + dr*58);
            float2 b = *(const float2*)(si + dr*58 + 2);
            v[dr][0]=a.x; v[dr][1]=a.y; v[dr][2]=b.x; v[dr][3]=b.y;
        }
        const float* wci = wg + ci*108;   // (ci*9 + t)*12
        #pragma unroll
        for (int t = 0; t < 9; t++){
            const int dr = t/3, dc = t%3;
            ull d0 = dup2(v[dr][dc]);
            ull d1 = dup2(v[dr][dc+1]);
            const float* wt = wci + t*12;
            ull wax, way, wbx, wby, wcx, wcy;
            ldg2(wt,     wax, way);
            ldg2(wt + 4, wbx, wby);
            ldg2(wt + 8, wcx, wcy);
            acc[0]  = fma2(d0, wax, acc[0]);
            acc[1]  = fma2(d0, way, acc[1]);
            acc[2]  = fma2(d0, wbx, acc[2]);
            acc[3]  = fma2(d0, wby, acc[3]);
            acc[4]  = fma2(d0, wcx, acc[4]);
            acc[5]  = fma2(d0, wcy, acc[5]);
            acc[6]  = fma2(d1, wax, acc[6]);
            acc[7]  = fma2(d1, way, acc[7]);
            acc[8]  = fma2(d1, wbx, acc[8]);
            acc[9]  = fma2(d1, wby, acc[9]);
            acc[10] = fma2(d1, wcx, acc[10]);
            acc[11] = fma2(d1, wcy, acc[11]);
        }
    }

    float af0[12], af1[12];
    #pragma unroll
    for (int i = 0; i < 6; i++){
        unpack2(acc[i],   af0[2*i], af0[2*i+1]);
        unpack2(acc[6+i], af1[2*i], af1[2*i+1]);
    }

    const int pix0 = (r0 + ty)*56 + 2*cx;     // even -> float2-aligned
    if (MODE == 0){
        #pragma unroll
        for (int k = 0; k < 12; k++){
            int idx = (cout_base + k)*HW + pix0;
            float2 xn = *(const float2*)(g_xnn + idx);
            float2 o;
            o.x = xn.x / (af0[k] + EPSF);
            o.y = xn.y / (af1[k] + EPSF);
            *(float2*)(g_t + idx) = o;
        }
    } else {
        float s0 = 0.f, s1 = 0.f;
        #pragma unroll
        for (int k = 0; k < 12; k++){
            int idx = (cout_base + k)*HW + pix0;
            float2 hv = *(const float2*)(g_h + idx);
            hv.x *= af0[k];
            hv.y *= af1[k];
            *(float2*)(g_h + idx) = hv;
            s0 += hv.x; s1 += hv.y;
        }
        float2 sv; sv.x = s0; sv.y = s1;
        *(float2*)(g_sum8 + gh*P + pbase + pix0) = sv;
    }
}

// ------- fused: x2 = x + h_norm  ->  LN2 over channels -> g_lncf [c][p] ---
__global__ void resid_ln2_kernel(const float* __restrict__ x,
                                 const float* __restrict__ lw,
                                 const float* __restrict__ lb){
    int p = blockIdx.x*256 + threadIdx.x;
    if (p >= P) return;
    int n = p / HW, hw = p % HW;
    float s = 0.f;
    #pragma unroll
    for (int j = 0; j < 8; j++) s += g_sum8[j*P + p];
    float inv = 1.0f / (s + EPSF);
    const float* xb = x   + n*C*HW + hw;
    const float* hb = g_h + n*C*HW + hw;
    float* tb = g_t + n*C*HW + hw;
    float s1 = 0.f, s2 = 0.f;
    for (int c = 0; c < C; c++){
        float v = xb[c*HW] + hb[c*HW]*inv;
        tb[c*HW] = v;
        s1 += v; s2 += v*v;
    }
    float u = s1 * (1.0f/96.0f);
    float var = s2 * (1.0f/96.0f) - u*u;
    float rs = rsqrtf(var + 1e-5f);
    for (int c = 0; c < C; c++)
        g_lncf[c*P + p] = (tb[c*HW] - u) * rs * lw[c] + lb[c];
}

// ---------------- GEMM1: [P,96] x [96,384] -> gelu -> g_hid --------------
__global__ __launch_bounds__(256) void gemm1_kernel(const float* __restrict__ w1,
                                                    const float* __restrict__ b1){
    __shared__ float As[96*68];
    __shared__ float Bs[96*32];
    const int tid = threadIdx.x;
    const int p0 = blockIdx.x * 64;
    const int n0 = blockIdx.y * 32;
    for (int i = tid; i < 6144; i += 256){
        int c = i >> 6, m = i & 63;
        As[c*68 + m] = g_lncf[c*P + p0 + m];
    }
    for (int i = tid; i < 3072; i += 256){
        int c = i >> 5, j = i & 31;
        Bs[c*32 + j] = w1[c*384 + n0 + j];
    }
    __syncthreads();
    const int tm = tid >> 4, tn = tid & 15;
    ull acc[4];
    #pragma unroll
    for (int i = 0; i < 4; i++) acc[i] = 0ULL;
    #pragma unroll 4
    for (int k = 0; k < 96; k++){
        float4 a = *(const float4*)(As + k*68 + tm*4);
        ull b = *(const ull*)(Bs + k*32 + tn*2);
        acc[0] = fma2(dup2(a.x), b, acc[0]);
        acc[1] = fma2(dup2(a.y), b, acc[1]);
        acc[2] = fma2(dup2(a.z), b, acc[2]);
        acc[3] = fma2(dup2(a.w), b, acc[3]);
    }
    int m = p0 + tm*4;
    int j = n0 + tn*2;
    float bj0 = b1[j], bj1 = b1[j+1];
    #pragma unroll
    for (int ii = 0; ii < 4; ii++){
        float a0, a1; unpack2(acc[ii], a0, a1);
        g_hid[(m+ii)*384 + j]     = gelu_exact(a0 + bj0);
        g_hid[(m+ii)*384 + j + 1] = gelu_exact(a1 + bj1);
    }
}

// ---- GEMM2: [P,384] x [384,96] + b2 + residual -> out (NCHW) -----------
__global__ __launch_bounds__(256) void gemm2_kernel(const float* __restrict__ w2,
                                                    const float* __restrict__ b2,
                                                    float* __restrict__ out){
    __shared__ float As[32*68];
    __shared__ float Bs[32*96];
    const int tid = threadIdx.x;
    const int p0 = blockIdx.x * 64;
    const int nimg = p0 / HW;
    const int hw0  = p0 % HW;
    const int tm = tid >> 4, tn = tid & 15;
    ull acc[4][3];
    #pragma unroll
    for (int ii = 0; ii < 4; ii++)
        #pragma unroll
        for (int jp = 0; jp < 3; jp++) acc[ii][jp] = 0ULL;
    for (int kb = 0; kb < 12; kb++){
        for (int i = tid; i < 2048; i += 256){
            int m = i >> 5, k = i & 31;
            As[k*68 + m] = g_hid[(p0 + m)*384 + kb*32 + k];
        }
        for (int i = tid; i < 3072; i += 256){
            int k = i / 96, c = i - k*96;
            Bs[k*96 + c] = w2[(kb*32 + k)*96 + c];
        }
        __syncthreads();
        #pragma unroll 4
        for (int k = 0; k < 32; k++){
            float4 a = *(const float4*)(As + k*68 + tm*4);
            const float* bp = Bs + k*96 + tn*6;
            ull b0 = *(const ull*)(bp);
            ull b1v = *(const ull*)(bp + 2);
            ull b2v = *(const ull*)(bp + 4);
            ull a0 = dup2(a.x), a1 = dup2(a.y), a2 = dup2(a.z), a3 = dup2(a.w);
            acc[0][0] = fma2(a0, b0, acc[0][0]);
            acc[0][1] = fma2(a0, b1v, acc[0][1]);
            acc[0][2] = fma2(a0, b2v, acc[0][2]);
            acc[1][0] = fma2(a1, b0, acc[1][0]);
            acc[1][1] = fma2(a1, b1v, acc[1][1]);
            acc[1][2] = fma2(a1, b2v, acc[1][2]);
            acc[2][0] = fma2(a2, b0, acc[2][0]);
            acc[2][1] = fma2(a2, b1v, acc[2][1]);
            acc[2][2] = fma2(a2, b2v, acc[2][2]);
            acc[3][0] = fma2(a3, b0, acc[3][0]);
            acc[3][1] = fma2(a3, b1v, acc[3][1]);
            acc[3][2] = fma2(a3, b2v, acc[3][2]);
        }
        __syncthreads();
    }
    const int cbase = tn*6;
    #pragma unroll
    for (int jp = 0; jp < 3; jp++){
        int c0 = cbase + 2*jp;
        float bc0 = b2[c0], bc1 = b2[c0+1];
        #pragma unroll
        for (int ii = 0; ii < 4; ii++){
            float v0, v1; unpack2(acc[ii][jp], v0, v1);
            int hw = hw0 + tm*4 + ii;
            int gi0 = (nimg*96 + c0)*HW + hw;
            int gi1 = (nimg*96 + c0 + 1)*HW + hw;
            out[gi0] = v0 + bc0 + g_t[gi0];
            out[gi1] = v1 + bc1 + g_t[gi1];
        }
    }
}

// ---------------- launch ----------------
extern "C" void kernel_launch(void* const* d_in, const int* in_sizes, int n_in,
                              void* d_out, int out_size){
    const float* x    = (const float*)d_in[0];
    const float* ln1w = (const float*)d_in[1];
    const float* ln1b = (const float*)d_in[2];
    const float* wn   = (const float*)d_in[3];
    const float* ln2w = (const float*)d_in[4];
    const float* ln2b = (const float*)d_in[5];
    const float* w1   = (const float*)d_in[6];
    const float* b1   = (const float*)d_in[7];
    const float* w2   = (const float*)d_in[8];
    const float* b2   = (const float*)d_in[9];
    float* out = (float*)d_out;

    const int CONV_SMEM = SM_TOT * 4;   // 58000 B
    cudaFuncSetAttribute(conv_kernel<0>, cudaFuncAttributeMaxDynamicSharedMemorySize, CONV_SMEM);
    cudaFuncSetAttribute(conv_kernel<1>, cudaFuncAttributeMaxDynamicSharedMemorySize, CONV_SMEM);

    prep_w_kernel<<<96, 32>>>(wn);
    ln1_kernel<<<98, 256>>>(x, ln1w, ln1b);

    dim3 cgrid(7, 8, 8);   // 448 blocks
    for (int it = 0; it < 25; ++it){
        conv_kernel<0><<<cgrid, 224, CONV_SMEM>>>();   // recon -> ratio
        conv_kernel<1><<<cgrid, 224, CONV_SMEM>>>();   // h update + partial sums
    }

    resid_ln2_kernel<<<98, 256>>>(x, ln2w, ln2b);
    gemm1_kernel<<<dim3(392, 12), 256>>>(w1, b1);
    gemm2_kernel<<<392, 256>>>(w2, b2, out);
}

// round 9
// speedup vs baseline: 1.5568x; 1.3230x over previous
#include <cuda_runtime.h>
#include <math.h>

#define NB 8
#define C 96
#define G 4
#define CG 24
#define HH 56
#define HW 3136
#define P 25088            // NB*HW
#define HD 384
#define NCHW (NB*C*HW)     // 2408448
#define EPSF 1e-12f

typedef unsigned long long ull;

__device__ __forceinline__ ull fma2(ull a, ull b, ull c){
    ull d; asm("fma.rn.f32x2 %0, %1, %2, %3;" : "=l"(d) : "l"(a), "l"(b), "l"(c));
    return d;
}
__device__ __forceinline__ ull dup2(float v){
    ull d; asm("mov.b64 %0, {%1, %1};" : "=l"(d) : "f"(v));
    return d;
}
__device__ __forceinline__ void unpack2(ull a, float& lo, float& hi){
    asm("mov.b64 {%0, %1}, %2;" : "=f"(lo), "=f"(hi) : "l"(a));
}

// ---------------- device scratch ----------------
__device__ float g_xnn[NCHW];     // relu(LN1(x)) channel-normalized
__device__ float g_h[NCHW];       // NNMF h (unnormalized; normalized on read)
__device__ float g_t[NCHW];       // ratio buffer, later x2 = x + attn
__device__ float g_lncf[NCHW];    // LN2 output, [c][p] channels-first
__device__ float g_hid[P*HD];     // MLP hidden
__device__ float g_wf2[8*2592];   // fwd weights  [g*2+hf][(ci*9+t)*12 + k]
__device__ float g_wb2[8*2592];   // bwd weights  [g*2+hf][(o*9+(8-t))*12 + k]
__device__ float g_sum8[8*P];     // per-(g,half) per-pixel partial sums of h

__device__ __forceinline__ float gelu_exact(float v){
    return 0.5f * v * (1.0f + erff(v * 0.70710678118654752f));
}

// ---------------- weight prep: |w| L1-normalized per out-channel ----------
__global__ void prep_w_kernel(const float* __restrict__ wn){
    int o = blockIdx.x;          // 0..95 global out channel
    int lane = threadIdx.x;      // 0..31
    float s = 0.f;
    for (int i = lane; i < 216; i += 32) s += fabsf(wn[o*216 + i]);
    #pragma unroll
    for (int off = 16; off; off >>= 1) s += __shfl_xor_sync(0xffffffffu, s, off);
    float inv = 1.0f / (s + EPSF);
    int g = o / 24, oo = o % 24;
    for (int i = lane; i < 216; i += 32){
        int ci = i / 9, t = i % 9;
        float v = fabsf(wn[o*216 + i]) * inv;
        g_wf2[(g*2 + oo/12)*2592 + (ci*9 + t)*12 + (oo%12)] = v;
        g_wb2[(g*2 + ci/12)*2592 + (oo*9 + (8 - t))*12 + (ci%12)] = v;
    }
}

// ---- LN1 (channels-first) + relu + channel-normalize; init h, sums ------
__global__ void ln1_kernel(const float* __restrict__ x,
                           const float* __restrict__ lw,
                           const float* __restrict__ lb){
    int p = blockIdx.x*256 + threadIdx.x;
    if (p >= P) return;
    int n = p / HW, hw = p % HW;
    const float* xb = x + n*C*HW + hw;
    float s1 = 0.f, s2 = 0.f;
    for (int c = 0; c < C; c++){ float v = xb[c*HW]; s1 += v; s2 += v*v; }
    float u = s1 * (1.0f/96.0f);
    float var = s2 * (1.0f/96.0f) - u*u;
    float rs = rsqrtf(var + 1e-6f);
    float sr = 0.f;
    for (int c = 0; c < C; c++){
        float v = (xb[c*HW] - u) * rs * lw[c] + lb[c];
        sr += fmaxf(v, 0.f);
    }
    float inv = 1.0f / (sr + EPSF);
    float* ob = g_xnn + n*C*HW + hw;
    float* hb = g_h   + n*C*HW + hw;
    for (int c = 0; c < C; c++){
        float v = (xb[c*HW] - u) * rs * lw[c] + lb[c];
        ob[c*HW] = fmaxf(v, 0.f) * inv;
        hb[c*HW] = 1.0f / 96.0f;
    }
    #pragma unroll
    for (int j = 0; j < 8; j++) g_sum8[j*P + p] = 0.125f;  // total = 1
}

// ---- grouped 3x3 conv: tile 8 rows x 56 cols, 2 ADJACENT px/thread ------
// grid (7 row-tiles, 8 (g,half), 8 n), block 224 = 8 rows x 28 col-pairs.
// Software-pipelined: weights double-buffered one tap ahead, inputs of ci+1
// prefetched during ci's FMAs (pad channel 24 + 12-float weight pad make the
// prefetch branch-free).
// MODE 0: transpose-conv of normalized h; epilogue ratio -> g_t (12 co)
// MODE 1: forward conv of ratio; epilogue h *= acc, partial sums -> g_sum8
#define SIN_F   (25*580)            // 14500 (incl. zero pad channel 24)
#define SW_OFF  SIN_F               // 14500
#define SW_F    (2592 + 12)         // 2604 (12-float zero pad)
#define SINV_OFF (SW_OFF + SW_F)    // 17104
#define SM_TOT  (SINV_OFF + 580)    // 17684 floats = 70736 B

template<int MODE>
__global__ __launch_bounds__(224, 3) void conv_kernel(){
    extern __shared__ float sm[];
    float* s_in  = sm;
    float* s_w   = sm + SW_OFF;
    float* s_inv = sm + SINV_OFF;
    const int tid = threadIdx.x;
    const int r0 = blockIdx.x * 8;
    const int gh = blockIdx.y;        // g*2 + half
    const int n  = blockIdx.z;
    const int g  = gh >> 1;
    const float* __restrict__ w  = ((MODE == 0) ? g_wb2 : g_wf2) + gh*2592;
    const float* __restrict__ in = (MODE == 0) ? g_h  : g_t;

    for (int i = tid; i < 2604; i += 224) s_w[i] = (i < 2592) ? w[i] : 0.f;
    // zero pad channel 24 (for branch-free input prefetch)
    for (int i = tid; i < 580; i += 224) s_in[24*580 + i] = 0.f;

    const int cin_base  = n*96 + g*24;
    const int cout_base = n*96 + g*24 + (gh & 1)*12;
    const int pbase = n*HW;

    if (MODE == 0){
        // per-halo-pixel inverse channel-sum (interior cols only; edges unused->0)
        for (int i = tid; i < 580; i += 224){
            int r   = i / 58;
            int col = i - r*58 - 1;
            int grow = r0 - 1 + r;
            float iv = 0.f;
            if ((unsigned)grow < 56u && (unsigned)col < 56u){
                int q = pbase + grow*56 + col;
                float s = 0.f;
                #pragma unroll
                for (int j = 0; j < 8; j++) s += g_sum8[j*P + q];
                iv = 1.0f / (s + EPSF);
            }
            s_inv[i] = iv;
        }
        __syncthreads();
    }

    // ---- edge halo columns are outside the image: always zero ----
    for (int i = tid; i < 480; i += 224){
        int ci = i / 20, rem = i - ci*20;
        int row = rem >> 1, ecol = (rem & 1) * 57;
        s_in[ci*580 + row*58 + ecol] = 0.f;
    }

    // ---- interior: vectorized LDG.128, guard hoisted out of ci loop ----
    {
        const int c4  = tid % 14;          // float4 slot within row
        const int rsl = tid / 14;          // smem row slot 0..15 (active <10)
        if (rsl < 10){
            const int grow = r0 - 1 + rsl;
            const bool rok = ((unsigned)grow < 56u);
            float iv0=0,iv1=0,iv2=0,iv3=0;
            if (MODE == 0 && rok){
                const float* sv = s_inv + rsl*58 + 1 + c4*4;
                iv0 = sv[0]; iv1 = sv[1]; iv2 = sv[2]; iv3 = sv[3];
            }
            const float* gb = in + (size_t)cin_base*HW + grow*56 + c4*4;
            float* sb = s_in + rsl*58 + 1 + c4*4;
            #pragma unroll 4
            for (int ci = 0; ci < 24; ci++){
                float4 v = make_float4(0.f,0.f,0.f,0.f);
                if (rok) v = *(const float4*)(gb + ci*HW);
                if (MODE == 0){ v.x*=iv0; v.y*=iv1; v.z*=iv2; v.w*=iv3; }
                float* s = sb + ci*580;
                s[0]=v.x; s[1]=v.y; s[2]=v.z; s[3]=v.w;
            }
        }
    }
    __syncthreads();

    const int cx = tid % 28;          // col-pair index: pixels 2cx, 2cx+1
    const int ty = tid / 28;          // 0..7
    const float* sbase = s_in + ty*58 + 2*cx;
    ull acc[12];                      // [0..5] px0 co-pairs, [6..11] px1
    #pragma unroll
    for (int i = 0; i < 12; i++) acc[i] = 0ULL;

    // prime: inputs of ci=0, weights of tap j=0
    float v[3][4], vn[3][4];
    #pragma unroll
    for (int dr = 0; dr < 3; dr++){
        float2 a = *(const float2*)(sbase + dr*58);
        float2 b = *(const float2*)(sbase + dr*58 + 2);
        v[dr][0]=a.x; v[dr][1]=a.y; v[dr][2]=b.x; v[dr][3]=b.y;
    }
    ulonglong2 wa, wb, wc;
    {
        const ulonglong2* wp = (const ulonglong2*)(s_w);
        wa = wp[0]; wb = wp[1]; wc = wp[2];
    }

    for (int ci = 0; ci < 24; ci++){
        // prefetch inputs of ci+1 (pad channel keeps this branch-free)
        const float* sn = sbase + (ci+1)*580;
        #pragma unroll
        for (int dr = 0; dr < 3; dr++){
            float2 a = *(const float2*)(sn + dr*58);
            float2 b = *(const float2*)(sn + dr*58 + 2);
            vn[dr][0]=a.x; vn[dr][1]=a.y; vn[dr][2]=b.x; vn[dr][3]=b.y;
        }
        #pragma unroll
        for (int t = 0; t < 9; t++){
            // prefetch next tap's weights (pad covers j=216)
            const ulonglong2* wp = (const ulonglong2*)(s_w + (ci*9 + t + 1)*12);
            ulonglong2 na = wp[0];
            ulonglong2 nb = wp[1];
            ulonglong2 nc = wp[2];
            const int dr = t/3, dc = t%3;
            ull d0 = dup2(v[dr][dc]);
            ull d1 = dup2(v[dr][dc+1]);
            acc[0]  = fma2(d0, wa.x, acc[0]);
            acc[1]  = fma2(d0, wa.y, acc[1]);
            acc[2]  = fma2(d0, wb.x, acc[2]);
            acc[3]  = fma2(d0, wb.y, acc[3]);
            acc[4]  = fma2(d0, wc.x, acc[4]);
            acc[5]  = fma2(d0, wc.y, acc[5]);
            acc[6]  = fma2(d1, wa.x, acc[6]);
            acc[7]  = fma2(d1, wa.y, acc[7]);
            acc[8]  = fma2(d1, wb.x, acc[8]);
            acc[9]  = fma2(d1, wb.y, acc[9]);
            acc[10] = fma2(d1, wc.x, acc[10]);
            acc[11] = fma2(d1, wc.y, acc[11]);
            wa = na; wb = nb; wc = nc;
        }
        #pragma unroll
        for (int dr = 0; dr < 3; dr++)
            #pragma unroll
            for (int q = 0; q < 4; q++) v[dr][q] = vn[dr][q];
    }

    float af0[12], af1[12];
    #pragma unroll
    for (int i = 0; i < 6; i++){
        unpack2(acc[i],   af0[2*i], af0[2*i+1]);
        unpack2(acc[6+i], af1[2*i], af1[2*i+1]);
    }

    const int pix0 = (r0 + ty)*56 + 2*cx;     // even -> float2-aligned
    if (MODE == 0){
        #pragma unroll
        for (int k = 0; k < 12; k++){
            int idx = (cout_base + k)*HW + pix0;
            float2 xn = *(const float2*)(g_xnn + idx);
            float2 o;
            o.x = xn.x / (af0[k] + EPSF);
            o.y = xn.y / (af1[k] + EPSF);
            *(float2*)(g_t + idx) = o;
        }
    } else {
        float s0 = 0.f, s1 = 0.f;
        #pragma unroll
        for (int k = 0; k < 12; k++){
            int idx = (cout_base + k)*HW + pix0;
            float2 hv = *(const float2*)(g_h + idx);
            hv.x *= af0[k];
            hv.y *= af1[k];
            *(float2*)(g_h + idx) = hv;
            s0 += hv.x; s1 += hv.y;
        }
        float2 sv; sv.x = s0; sv.y = s1;
        *(float2*)(g_sum8 + gh*P + pbase + pix0) = sv;
    }
}

// ------- fused: x2 = x + h_norm  ->  LN2 over channels -> g_lncf [c][p] ---
__global__ void resid_ln2_kernel(const float* __restrict__ x,
                                 const float* __restrict__ lw,
                                 const float* __restrict__ lb){
    int p = blockIdx.x*256 + threadIdx.x;
    if (p >= P) return;
    int n = p / HW, hw = p % HW;
    float s = 0.f;
    #pragma unroll
    for (int j = 0; j < 8; j++) s += g_sum8[j*P + p];
    float inv = 1.0f / (s + EPSF);
    const float* xb = x   + n*C*HW + hw;
    const float* hb = g_h + n*C*HW + hw;
    float* tb = g_t + n*C*HW + hw;
    float s1 = 0.f, s2 = 0.f;
    for (int c = 0; c < C; c++){
        float v = xb[c*HW] + hb[c*HW]*inv;
        tb[c*HW] = v;
        s1 += v; s2 += v*v;
    }
    float u = s1 * (1.0f/96.0f);
    float var = s2 * (1.0f/96.0f) - u*u;
    float rs = rsqrtf(var + 1e-5f);
    for (int c = 0; c < C; c++)
        g_lncf[c*P + p] = (tb[c*HW] - u) * rs * lw[c] + lb[c];
}

// ---------------- GEMM1: [P,96] x [96,384] -> gelu -> g_hid --------------
__global__ __launch_bounds__(256) void gemm1_kernel(const float* __restrict__ w1,
                                                    const float* __restrict__ b1){
    __shared__ float As[96*68];
    __shared__ float Bs[96*32];
    const int tid = threadIdx.x;
    const int p0 = blockIdx.x * 64;
    const int n0 = blockIdx.y * 32;
    for (int i = tid; i < 6144; i += 256){
        int c = i >> 6, m = i & 63;
        As[c*68 + m] = g_lncf[c*P + p0 + m];
    }
    for (int i = tid; i < 3072; i += 256){
        int c = i >> 5, j = i & 31;
        Bs[c*32 + j] = w1[c*384 + n0 + j];
    }
    __syncthreads();
    const int tm = tid >> 4, tn = tid & 15;
    ull acc[4];
    #pragma unroll
    for (int i = 0; i < 4; i++) acc[i] = 0ULL;
    #pragma unroll 4
    for (int k = 0; k < 96; k++){
        float4 a = *(const float4*)(As + k*68 + tm*4);
        ull b = *(const ull*)(Bs + k*32 + tn*2);
        acc[0] = fma2(dup2(a.x), b, acc[0]);
        acc[1] = fma2(dup2(a.y), b, acc[1]);
        acc[2] = fma2(dup2(a.z), b, acc[2]);
        acc[3] = fma2(dup2(a.w), b, acc[3]);
    }
    int m = p0 + tm*4;
    int j = n0 + tn*2;
    float bj0 = b1[j], bj1 = b1[j+1];
    #pragma unroll
    for (int ii = 0; ii < 4; ii++){
        float a0, a1; unpack2(acc[ii], a0, a1);
        g_hid[(m+ii)*384 + j]     = gelu_exact(a0 + bj0);
        g_hid[(m+ii)*384 + j + 1] = gelu_exact(a1 + bj1);
    }
}

// ---- GEMM2: [P,384] x [384,96] + b2 + residual -> out (NCHW) -----------
__global__ __launch_bounds__(256) void gemm2_kernel(const float* __restrict__ w2,
                                                    const float* __restrict__ b2,
                                                    float* __restrict__ out){
    __shared__ float As[32*68];
    __shared__ float Bs[32*96];
    const int tid = threadIdx.x;
    const int p0 = blockIdx.x * 64;
    const int nimg = p0 / HW;
    const int hw0  = p0 % HW;
    const int tm = tid >> 4, tn = tid & 15;
    ull acc[4][3];
    #pragma unroll
    for (int ii = 0; ii < 4; ii++)
        #pragma unroll
        for (int jp = 0; jp < 3; jp++) acc[ii][jp] = 0ULL;
    for (int kb = 0; kb < 12; kb++){
        for (int i = tid; i < 2048; i += 256){
            int m = i >> 5, k = i & 31;
            As[k*68 + m] = g_hid[(p0 + m)*384 + kb*32 + k];
        }
        for (int i = tid; i < 3072; i += 256){
            int k = i / 96, c = i - k*96;
            Bs[k*96 + c] = w2[(kb*32 + k)*96 + c];
        }
        __syncthreads();
        #pragma unroll 4
        for (int k = 0; k < 32; k++){
            float4 a = *(const float4*)(As + k*68 + tm*4);
            const float* bp = Bs + k*96 + tn*6;
            ull b0 = *(const ull*)(bp);
            ull b1v = *(const ull*)(bp + 2);
            ull b2v = *(const ull*)(bp + 4);
            ull a0 = dup2(a.x), a1 = dup2(a.y), a2 = dup2(a.z), a3 = dup2(a.w);
            acc[0][0] = fma2(a0, b0, acc[0][0]);
            acc[0][1] = fma2(a0, b1v, acc[0][1]);
            acc[0][2] = fma2(a0, b2v, acc[0][2]);
            acc[1][0] = fma2(a1, b0, acc[1][0]);
            acc[1][1] = fma2(a1, b1v, acc[1][1]);
            acc[1][2] = fma2(a1, b2v, acc[1][2]);
            acc[2][0] = fma2(a2, b0, acc[2][0]);
            acc[2][1] = fma2(a2, b1v, acc[2][1]);
            acc[2][2] = fma2(a2, b2v, acc[2][2]);
            acc[3][0] = fma2(a3, b0, acc[3][0]);
            acc[3][1] = fma2(a3, b1v, acc[3][1]);
            acc[3][2] = fma2(a3, b2v, acc[3][2]);
        }
        __syncthreads();
    }
    const int cbase = tn*6;
    #pragma unroll
    for (int jp = 0; jp < 3; jp++){
        int c0 = cbase + 2*jp;
        float bc0 = b2[c0], bc1 = b2[c0+1];
        #pragma unroll
        for (int ii = 0; ii < 4; ii++){
            float v0, v1; unpack2(acc[ii][jp], v0, v1);
            int hw = hw0 + tm*4 + ii;
            int gi0 = (nimg*96 + c0)*HW + hw;
            int gi1 = (nimg*96 + c0 + 1)*HW + hw;
            out[gi0] = v0 + bc0 + g_t[gi0];
            out[gi1] = v1 + bc1 + g_t[gi1];
        }
    }
}

// ---------------- launch ----------------
extern "C" void kernel_launch(void* const* d_in, const int* in_sizes, int n_in,
                              void* d_out, int out_size){
    const float* x    = (const float*)d_in[0];
    const float* ln1w = (const float*)d_in[1];
    const float* ln1b = (const float*)d_in[2];
    const float* wn   = (const float*)d_in[3];
    const float* ln2w = (const float*)d_in[4];
    const float* ln2b = (const float*)d_in[5];
    const float* w1   = (const float*)d_in[6];
    const float* b1   = (const float*)d_in[7];
    const float* w2   = (const float*)d_in[8];
    const float* b2   = (const float*)d_in[9];
    float* out = (float*)d_out;

    const int CONV_SMEM = SM_TOT * 4;   // 70736 B
    cudaFuncSetAttribute(conv_kernel<0>, cudaFuncAttributeMaxDynamicSharedMemorySize, CONV_SMEM);
    cudaFuncSetAttribute(conv_kernel<1>, cudaFuncAttributeMaxDynamicSharedMemorySize, CONV_SMEM);

    prep_w_kernel<<<96, 32>>>(wn);
    ln1_kernel<<<98, 256>>>(x, ln1w, ln1b);

    dim3 cgrid(7, 8, 8);   // 448 blocks
    for (int it = 0; it < 25; ++it){
        conv_kernel<0><<<cgrid, 224, CONV_SMEM>>>();   // recon -> ratio
        conv_kernel<1><<<cgrid, 224, CONV_SMEM>>>();   // h update + partial sums
    }

    resid_ln2_kernel<<<98, 256>>>(x, ln2w, ln2b);
    gemm1_kernel<<<dim3(392, 12), 256>>>(w1, b1);
    gemm2_kernel<<<392, 256>>>(w2, b2, out);
}